// round 1
// baseline (speedup 1.0000x reference)
#include <cuda_runtime.h>

#define BB 2
#define LL 8192
#define HH 16
#define DD 64
#define CC 64
#define NCH 128                    // LL/CC
#define NW  (BB*NCH*HH)            // 4096 chunk-head work items
#define YSIZE ((size_t)BB*LL*HH*2*DD)   // 33,554,432

// Scratch (no allocations allowed): per-chunk final state + total gate
__device__ float g_hfin[(size_t)NW * 128];  // 2 MB: [w][row(2)][d(64)]
__device__ float g_At[(size_t)NW * 4];      // 64 KB: [w][2][2]

// ---------------------------------------------------------------------------
// Pass 1: intra-chunk scan; emit final_h (2x64) and total_A (2x2) per chunk.
// One warp per (b, chunk, h); lane handles d = {2*lane, 2*lane+1}.
// ---------------------------------------------------------------------------
__global__ __launch_bounds__(128) void k_local1(
    const float* __restrict__ Ag, const float* __restrict__ Kg,
    const float* __restrict__ Vg, const float* __restrict__ Bg)
{
    int w    = (blockIdx.x * 128 + threadIdx.x) >> 5;
    int lane = threadIdx.x & 31;
    int h = w % HH;
    int c = (w / HH) % NCH;
    int b = w / (HH * NCH);

    float h0a = 0.f, h0b = 0.f, h1a = 0.f, h1b = 0.f;
    float p00 = 1.f, p01 = 0.f, p10 = 0.f, p11 = 1.f;

    size_t base = ((size_t)b * LL + (size_t)c * CC) * HH + h;

#pragma unroll 4
    for (int t = 0; t < CC; t++) {
        size_t idx = base + (size_t)t * HH;
        float4 a  = __ldg((const float4*)(Ag + idx * 4));
        float2 v  = __ldg((const float2*)(Vg + idx * 2));
        float  bt = __ldg(Bg + idx);
        float2 kk = __ldg((const float2*)(Kg + idx * 64 + 2 * lane));

        float hp0a = a.x * h0a + a.y * h1a;
        float hp0b = a.x * h0b + a.y * h1b;
        float hp1a = a.z * h0a + a.w * h1a;
        float hp1b = a.z * h0b + a.w * h1b;

        float r0 = hp0a * kk.x + hp0b * kk.y;
        float r1 = hp1a * kk.x + hp1b * kk.y;
#pragma unroll
        for (int o = 16; o; o >>= 1) {
            r0 += __shfl_xor_sync(0xffffffffu, r0, o);
            r1 += __shfl_xor_sync(0xffffffffu, r1, o);
        }

        float d0 = bt * (v.x - r0);
        float d1 = bt * (v.y - r1);
        h0a = hp0a + d0 * kk.x;  h0b = hp0b + d0 * kk.y;
        h1a = hp1a + d1 * kk.x;  h1b = hp1b + d1 * kk.y;

        float q00 = a.x * p00 + a.y * p10;
        float q01 = a.x * p01 + a.y * p11;
        float q10 = a.z * p00 + a.w * p10;
        float q11 = a.z * p01 + a.w * p11;
        p00 = q00; p01 = q01; p10 = q10; p11 = q11;
    }

    float* hf = g_hfin + (size_t)w * 128;
    ((float2*)hf)[lane]        = make_float2(h0a, h0b);
    ((float2*)(hf + 64))[lane] = make_float2(h1a, h1b);
    if (lane == 0) {
        float* at = g_At + (size_t)w * 4;
        at[0] = p00; at[1] = p01; at[2] = p10; at[3] = p11;
    }
}

// ---------------------------------------------------------------------------
// Pass 2: inter-chunk scan per (b,h); writes chunk_states (pre-update carry)
// straight into the output tail. Loads are carry-independent -> pipelined.
// ---------------------------------------------------------------------------
__global__ __launch_bounds__(64) void k_inter(float* __restrict__ cs)
{
    int b = blockIdx.x / HH;
    int h = blockIdx.x % HH;
    int d = threadIdx.x;

    float s0 = 0.f, s1 = 0.f;
#pragma unroll 8
    for (int c = 0; c < NCH; c++) {
        size_t w = ((size_t)b * NCH + c) * HH + h;
        cs[(w * 2 + 0) * 64 + d] = s0;
        cs[(w * 2 + 1) * 64 + d] = s1;
        const float* at = g_At + w * 4;
        float a00 = at[0], a01 = at[1], a10 = at[2], a11 = at[3];
        float hf0 = g_hfin[w * 128 + d];
        float hf1 = g_hfin[w * 128 + 64 + d];
        float n0 = a00 * s0 + a01 * s1 + hf0;
        float n1 = a10 * s0 + a11 * s1 + hf1;
        s0 = n0; s1 = n1;
    }
}

// ---------------------------------------------------------------------------
// Pass 3: redo the intra scan, apply Y_t = local_h_t + P_t @ s_chunk, stream Y.
// ---------------------------------------------------------------------------
__global__ __launch_bounds__(128) void k_local2(
    const float* __restrict__ Ag, const float* __restrict__ Kg,
    const float* __restrict__ Vg, const float* __restrict__ Bg,
    const float* __restrict__ cs, float* __restrict__ Y)
{
    int w    = (blockIdx.x * 128 + threadIdx.x) >> 5;
    int lane = threadIdx.x & 31;
    int h = w % HH;
    int c = (w / HH) % NCH;
    int b = w / (HH * NCH);

    const float2* sp = (const float2*)(cs + (size_t)w * 128);
    float2 S0 = __ldg(sp + lane);        // s[0][2l], s[0][2l+1]
    float2 S1 = __ldg(sp + 32 + lane);   // s[1][2l], s[1][2l+1]

    float h0a = 0.f, h0b = 0.f, h1a = 0.f, h1b = 0.f;
    float p00 = 1.f, p01 = 0.f, p10 = 0.f, p11 = 1.f;

    size_t base = ((size_t)b * LL + (size_t)c * CC) * HH + h;

#pragma unroll 4
    for (int t = 0; t < CC; t++) {
        size_t idx = base + (size_t)t * HH;
        float4 a  = __ldg((const float4*)(Ag + idx * 4));
        float2 v  = __ldg((const float2*)(Vg + idx * 2));
        float  bt = __ldg(Bg + idx);
        float2 kk = __ldg((const float2*)(Kg + idx * 64 + 2 * lane));

        float hp0a = a.x * h0a + a.y * h1a;
        float hp0b = a.x * h0b + a.y * h1b;
        float hp1a = a.z * h0a + a.w * h1a;
        float hp1b = a.z * h0b + a.w * h1b;

        float r0 = hp0a * kk.x + hp0b * kk.y;
        float r1 = hp1a * kk.x + hp1b * kk.y;
#pragma unroll
        for (int o = 16; o; o >>= 1) {
            r0 += __shfl_xor_sync(0xffffffffu, r0, o);
            r1 += __shfl_xor_sync(0xffffffffu, r1, o);
        }

        float d0 = bt * (v.x - r0);
        float d1 = bt * (v.y - r1);
        h0a = hp0a + d0 * kk.x;  h0b = hp0b + d0 * kk.y;
        h1a = hp1a + d1 * kk.x;  h1b = hp1b + d1 * kk.y;

        float q00 = a.x * p00 + a.y * p10;
        float q01 = a.x * p01 + a.y * p11;
        float q10 = a.z * p00 + a.w * p10;
        float q11 = a.z * p01 + a.w * p11;
        p00 = q00; p01 = q01; p10 = q10; p11 = q11;

        float y0a = h0a + p00 * S0.x + p01 * S1.x;
        float y0b = h0b + p00 * S0.y + p01 * S1.y;
        float y1a = h1a + p10 * S0.x + p11 * S1.x;
        float y1b = h1b + p10 * S0.y + p11 * S1.y;

        float2* yo = (float2*)(Y + idx * 128);
        __stcs(yo + lane,      make_float2(y0a, y0b));
        __stcs(yo + 32 + lane, make_float2(y1a, y1b));
    }
}

extern "C" void kernel_launch(void* const* d_in, const int* in_sizes, int n_in,
                              void* d_out, int out_size)
{
    const float* A    = (const float*)d_in[0];
    const float* K    = (const float*)d_in[1];
    const float* V    = (const float*)d_in[2];
    const float* beta = (const float*)d_in[3];
    float* Y  = (float*)d_out;
    float* cs = Y + YSIZE;   // chunk_states tail of the output buffer

    k_local1<<<NW / 4, 128>>>(A, K, V, beta);
    k_inter<<<BB * HH, 64>>>(cs);
    k_local2<<<NW / 4, 128>>>(A, K, V, beta, cs, Y);
}

// round 3
// speedup vs baseline: 1.2211x; 1.2211x over previous
#include <cuda_runtime.h>

#define BB 2
#define LL 8192
#define HH 16
#define DD 64
#define CC 64
#define NCH 128                    // LL/CC
#define NW  (BB*NCH*HH)            // 4096 chunk-head work items
#define YSIZE ((size_t)BB*LL*HH*2*DD)   // 33,554,432
#define PF 8                       // prefetch depth (divides CC)

// Scratch (no allocations allowed): per-chunk final state + total gate
__device__ float g_hfin[(size_t)NW * 128];  // 2 MB: [w][row(2)][d(64)]
__device__ float g_At[(size_t)NW * 4];      // 64 KB: [w][2][2]

// ---------------------------------------------------------------------------
// Pass 1: intra-chunk scan; emit final_h (2x64) and total_A (2x2) per chunk.
// One warp per (b, chunk, h); lane handles d = {2*lane, 2*lane+1}.
// 8-deep register prefetch pipeline hides DRAM latency behind the scan chain.
// ---------------------------------------------------------------------------
__global__ __launch_bounds__(128) void k_local1(
    const float* __restrict__ Ag, const float* __restrict__ Kg,
    const float* __restrict__ Vg, const float* __restrict__ Bg)
{
    int w    = (blockIdx.x * 128 + threadIdx.x) >> 5;
    int lane = threadIdx.x & 31;
    int h = w % HH;
    int c = (w / HH) % NCH;
    int b = w / (HH * NCH);

    size_t base = ((size_t)b * LL + (size_t)c * CC) * HH + h;

    float4 aB[PF]; float2 vB[PF]; float bBf[PF]; float2 kB[PF];
#pragma unroll
    for (int i = 0; i < PF; i++) {
        size_t idx = base + (size_t)i * HH;
        aB[i]  = __ldg((const float4*)(Ag + idx * 4));
        vB[i]  = __ldg((const float2*)(Vg + idx * 2));
        bBf[i] = __ldg(Bg + idx);
        kB[i]  = __ldg((const float2*)(Kg + idx * 64 + 2 * lane));
    }

    float h0a = 0.f, h0b = 0.f, h1a = 0.f, h1b = 0.f;
    float p00 = 1.f, p01 = 0.f, p10 = 0.f, p11 = 1.f;

    for (int t = 0; t < CC; t += PF) {
#pragma unroll
        for (int u = 0; u < PF; u++) {
            float4 a  = aB[u];
            float2 v  = vB[u];
            float  bt = bBf[u];
            float2 kk = kB[u];

            int tn = t + u + PF;
            if (tn < CC) {
                size_t idx = base + (size_t)tn * HH;
                aB[u]  = __ldg((const float4*)(Ag + idx * 4));
                vB[u]  = __ldg((const float2*)(Vg + idx * 2));
                bBf[u] = __ldg(Bg + idx);
                kB[u]  = __ldg((const float2*)(Kg + idx * 64 + 2 * lane));
            }

            float hp0a = a.x * h0a + a.y * h1a;
            float hp0b = a.x * h0b + a.y * h1b;
            float hp1a = a.z * h0a + a.w * h1a;
            float hp1b = a.z * h0b + a.w * h1b;

            float r0 = hp0a * kk.x + hp0b * kk.y;
            float r1 = hp1a * kk.x + hp1b * kk.y;
#pragma unroll
            for (int o = 16; o; o >>= 1) {
                r0 += __shfl_xor_sync(0xffffffffu, r0, o);
                r1 += __shfl_xor_sync(0xffffffffu, r1, o);
            }

            float d0 = bt * (v.x - r0);
            float d1 = bt * (v.y - r1);
            h0a = hp0a + d0 * kk.x;  h0b = hp0b + d0 * kk.y;
            h1a = hp1a + d1 * kk.x;  h1b = hp1b + d1 * kk.y;

            float q00 = a.x * p00 + a.y * p10;
            float q01 = a.x * p01 + a.y * p11;
            float q10 = a.z * p00 + a.w * p10;
            float q11 = a.z * p01 + a.w * p11;
            p00 = q00; p01 = q01; p10 = q10; p11 = q11;
        }
    }

    float* hf = g_hfin + (size_t)w * 128;
    ((float2*)hf)[lane]        = make_float2(h0a, h0b);
    ((float2*)(hf + 64))[lane] = make_float2(h1a, h1b);
    if (lane == 0) {
        float* at = g_At + (size_t)w * 4;
        at[0] = p00; at[1] = p01; at[2] = p10; at[3] = p11;
    }
}

// ---------------------------------------------------------------------------
// Pass 2: inter-chunk scan per (b,h); writes chunk_states (pre-update carry)
// straight into the output tail. Loads are carry-independent -> pipelined.
// ---------------------------------------------------------------------------
__global__ __launch_bounds__(64) void k_inter(float* __restrict__ cs)
{
    int b = blockIdx.x / HH;
    int h = blockIdx.x % HH;
    int d = threadIdx.x;

    float s0 = 0.f, s1 = 0.f;
#pragma unroll 8
    for (int c = 0; c < NCH; c++) {
        size_t w = ((size_t)b * NCH + c) * HH + h;
        cs[(w * 2 + 0) * 64 + d] = s0;
        cs[(w * 2 + 1) * 64 + d] = s1;
        const float* at = g_At + w * 4;
        float a00 = at[0], a01 = at[1], a10 = at[2], a11 = at[3];
        float hf0 = g_hfin[w * 128 + d];
        float hf1 = g_hfin[w * 128 + 64 + d];
        float n0 = a00 * s0 + a01 * s1 + hf0;
        float n1 = a10 * s0 + a11 * s1 + hf1;
        s0 = n0; s1 = n1;
    }
}

// ---------------------------------------------------------------------------
// Pass 3: redo the intra scan, apply Y_t = local_h_t + P_t @ s_chunk, stream Y.
// Same prefetch pipeline as pass 1.
// ---------------------------------------------------------------------------
__global__ __launch_bounds__(128) void k_local2(
    const float* __restrict__ Ag, const float* __restrict__ Kg,
    const float* __restrict__ Vg, const float* __restrict__ Bg,
    const float* __restrict__ cs, float* __restrict__ Y)
{
    int w    = (blockIdx.x * 128 + threadIdx.x) >> 5;
    int lane = threadIdx.x & 31;
    int h = w % HH;
    int c = (w / HH) % NCH;
    int b = w / (HH * NCH);

    const float2* sp = (const float2*)(cs + (size_t)w * 128);
    float2 S0 = __ldg(sp + lane);        // s[0][2l], s[0][2l+1]
    float2 S1 = __ldg(sp + 32 + lane);   // s[1][2l], s[1][2l+1]

    size_t base = ((size_t)b * LL + (size_t)c * CC) * HH + h;

    float4 aB[PF]; float2 vB[PF]; float bBf[PF]; float2 kB[PF];
#pragma unroll
    for (int i = 0; i < PF; i++) {
        size_t idx = base + (size_t)i * HH;
        aB[i]  = __ldg((const float4*)(Ag + idx * 4));
        vB[i]  = __ldg((const float2*)(Vg + idx * 2));
        bBf[i] = __ldg(Bg + idx);
        kB[i]  = __ldg((const float2*)(Kg + idx * 64 + 2 * lane));
    }

    float h0a = 0.f, h0b = 0.f, h1a = 0.f, h1b = 0.f;
    float p00 = 1.f, p01 = 0.f, p10 = 0.f, p11 = 1.f;

    for (int t = 0; t < CC; t += PF) {
#pragma unroll
        for (int u = 0; u < PF; u++) {
            float4 a  = aB[u];
            float2 v  = vB[u];
            float  bt = bBf[u];
            float2 kk = kB[u];

            int tn = t + u + PF;
            if (tn < CC) {
                size_t idx = base + (size_t)tn * HH;
                aB[u]  = __ldg((const float4*)(Ag + idx * 4));
                vB[u]  = __ldg((const float2*)(Vg + idx * 2));
                bBf[u] = __ldg(Bg + idx);
                kB[u]  = __ldg((const float2*)(Kg + idx * 64 + 2 * lane));
            }

            float hp0a = a.x * h0a + a.y * h1a;
            float hp0b = a.x * h0b + a.y * h1b;
            float hp1a = a.z * h0a + a.w * h1a;
            float hp1b = a.z * h0b + a.w * h1b;

            float r0 = hp0a * kk.x + hp0b * kk.y;
            float r1 = hp1a * kk.x + hp1b * kk.y;
#pragma unroll
            for (int o = 16; o; o >>= 1) {
                r0 += __shfl_xor_sync(0xffffffffu, r0, o);
                r1 += __shfl_xor_sync(0xffffffffu, r1, o);
            }

            float d0 = bt * (v.x - r0);
            float d1 = bt * (v.y - r1);
            h0a = hp0a + d0 * kk.x;  h0b = hp0b + d0 * kk.y;
            h1a = hp1a + d1 * kk.x;  h1b = hp1b + d1 * kk.y;

            float q00 = a.x * p00 + a.y * p10;
            float q01 = a.x * p01 + a.y * p11;
            float q10 = a.z * p00 + a.w * p10;
            float q11 = a.z * p01 + a.w * p11;
            p00 = q00; p01 = q01; p10 = q10; p11 = q11;

            float y0a = h0a + p00 * S0.x + p01 * S1.x;
            float y0b = h0b + p00 * S0.y + p01 * S1.y;
            float y1a = h1a + p10 * S0.x + p11 * S1.x;
            float y1b = h1b + p10 * S0.y + p11 * S1.y;

            size_t idx = base + (size_t)(t + u) * HH;
            float2* yo = (float2*)(Y + idx * 128);
            __stcs(yo + lane,      make_float2(y0a, y0b));
            __stcs(yo + 32 + lane, make_float2(y1a, y1b));
        }
    }
}

extern "C" void kernel_launch(void* const* d_in, const int* in_sizes, int n_in,
                              void* d_out, int out_size)
{
    const float* A    = (const float*)d_in[0];
    const float* K    = (const float*)d_in[1];
    const float* V    = (const float*)d_in[2];
    const float* beta = (const float*)d_in[3];
    float* Y  = (float*)d_out;
    float* cs = Y + YSIZE;   // chunk_states tail of the output buffer

    k_local1<<<NW / 4, 128>>>(A, K, V, beta);
    k_inter<<<BB * HH, 64>>>(cs);
    k_local2<<<NW / 4, 128>>>(A, K, V, beta, cs, Y);
}

// round 4
// speedup vs baseline: 1.2486x; 1.0226x over previous
#include <cuda_runtime.h>

#define BB 2
#define LL 8192
#define HH 16
#define DD 64
#define CC 64
#define NCH 128                    // LL/CC
#define NW  (BB*NCH*HH)            // 4096 chunk-head work items
#define YSIZE ((size_t)BB*LL*HH*2*DD)   // 33,554,432
#define PF 8                       // prefetch depth (divides CC)

// Scratch: per-chunk final state + total gate
__device__ float g_hfin[(size_t)NW * 128];  // [w][row(2)][d(64)]
__device__ float g_At[(size_t)NW * 4];      // [w][2][2]

__device__ __forceinline__ float4 f4fma(float s, float4 x, float4 acc) {
    return make_float4(fmaf(s, x.x, acc.x), fmaf(s, x.y, acc.y),
                       fmaf(s, x.z, acc.z), fmaf(s, x.w, acc.w));
}

// ---------------------------------------------------------------------------
// Intra-chunk scan core. TWO chunk-heads per warp: lanes 0-15 -> head 2w,
// lanes 16-31 -> head 2w+1. Each lane owns d = 4g..4g+3 (g = lane&15) as a
// float4. Reduction = 4 butterfly levels confined to the half-warp.
// 8-deep register prefetch hides memory latency behind the scan chain.
// ---------------------------------------------------------------------------
template<bool EMIT_Y>
__device__ __forceinline__ void intra_scan(
    const float* __restrict__ Ag, const float* __restrict__ Kg,
    const float* __restrict__ Vg, const float* __restrict__ Bg,
    const float* __restrict__ cs, float* __restrict__ Y)
{
    int warp = (blockIdx.x * blockDim.x + threadIdx.x) >> 5;
    int lane = threadIdx.x & 31;
    int g    = lane & 15;
    int hd   = 2 * warp + (lane >> 4);       // chunk-head id for this half-warp

    int h = hd % HH;
    int c = (hd / HH) % NCH;
    int b = hd / (HH * NCH);
    size_t base = ((size_t)b * LL + (size_t)c * CC) * HH + h;

    float4 aB[PF]; float2 vB[PF]; float bB[PF]; float4 kB[PF];
#pragma unroll
    for (int i = 0; i < PF; i++) {
        size_t idx = base + (size_t)i * HH;
        aB[i] = __ldg((const float4*)(Ag + idx * 4));
        vB[i] = __ldg((const float2*)(Vg + idx * 2));
        bB[i] = __ldg(Bg + idx);
        kB[i] = __ldg((const float4*)(Kg + idx * 64 + 4 * g));
    }

    float4 S0, S1;
    if (EMIT_Y) {
        const float4* sp = (const float4*)(cs + (size_t)hd * 128);
        S0 = __ldg(sp + g);
        S1 = __ldg(sp + 16 + g);
    }

    float4 h0 = make_float4(0.f, 0.f, 0.f, 0.f);
    float4 h1 = make_float4(0.f, 0.f, 0.f, 0.f);
    float p00 = 1.f, p01 = 0.f, p10 = 0.f, p11 = 1.f;

    for (int t = 0; t < CC; t += PF) {
#pragma unroll
        for (int u = 0; u < PF; u++) {
            float4 a  = aB[u];
            float2 v  = vB[u];
            float  bt = bB[u];
            float4 kk = kB[u];

            int tn = t + u + PF;
            if (tn < CC) {
                size_t idx = base + (size_t)tn * HH;
                aB[u] = __ldg((const float4*)(Ag + idx * 4));
                vB[u] = __ldg((const float2*)(Vg + idx * 2));
                bB[u] = __ldg(Bg + idx);
                kB[u] = __ldg((const float4*)(Kg + idx * 64 + 4 * g));
            }

            // propagate: hp = A * h   (2x2 gate applied per d-element)
            float4 hp0 = f4fma(a.y, h1, make_float4(a.x*h0.x, a.x*h0.y, a.x*h0.z, a.x*h0.w));
            float4 hp1 = f4fma(a.w, h1, make_float4(a.z*h0.x, a.z*h0.y, a.z*h0.z, a.z*h0.w));

            // read = k . hp  (partial over 4 elems, then 4-level half-warp reduce)
            float r0 = hp0.x*kk.x + hp0.y*kk.y + hp0.z*kk.z + hp0.w*kk.w;
            float r1 = hp1.x*kk.x + hp1.y*kk.y + hp1.z*kk.z + hp1.w*kk.w;
#pragma unroll
            for (int o = 8; o; o >>= 1) {
                r0 += __shfl_xor_sync(0xffffffffu, r0, o);
                r1 += __shfl_xor_sync(0xffffffffu, r1, o);
            }

            float d0 = bt * (v.x - r0);
            float d1 = bt * (v.y - r1);
            h0 = f4fma(d0, kk, hp0);
            h1 = f4fma(d1, kk, hp1);

            // cumulative 2x2 gate product
            float q00 = a.x * p00 + a.y * p10;
            float q01 = a.x * p01 + a.y * p11;
            float q10 = a.z * p00 + a.w * p10;
            float q11 = a.z * p01 + a.w * p11;
            p00 = q00; p01 = q01; p10 = q10; p11 = q11;

            if (EMIT_Y) {
                float4 y0 = f4fma(p01, S1, f4fma(p00, S0, h0));
                float4 y1 = f4fma(p11, S1, f4fma(p10, S0, h1));
                size_t idx = base + (size_t)(t + u) * HH;
                float4* yo = (float4*)(Y + idx * 128);
                __stcs(yo + g,      y0);
                __stcs(yo + 16 + g, y1);
            }
        }
    }

    if (!EMIT_Y) {
        float* hf = g_hfin + (size_t)hd * 128;
        ((float4*)hf)[g]        = h0;
        ((float4*)(hf + 64))[g] = h1;
        if (g == 0) {
            float* at = g_At + (size_t)hd * 4;
            at[0] = p00; at[1] = p01; at[2] = p10; at[3] = p11;
        }
    }
}

__global__ __launch_bounds__(128) void k_local1(
    const float* __restrict__ Ag, const float* __restrict__ Kg,
    const float* __restrict__ Vg, const float* __restrict__ Bg)
{
    intra_scan<false>(Ag, Kg, Vg, Bg, nullptr, nullptr);
}

__global__ __launch_bounds__(128) void k_local2(
    const float* __restrict__ Ag, const float* __restrict__ Kg,
    const float* __restrict__ Vg, const float* __restrict__ Bg,
    const float* __restrict__ cs, float* __restrict__ Y)
{
    intra_scan<true>(Ag, Kg, Vg, Bg, cs, Y);
}

// ---------------------------------------------------------------------------
// Inter-chunk scan per (b,h); writes chunk_states (pre-update carry) straight
// into the output tail. Loads are carry-independent -> pipelined by unroll.
// ---------------------------------------------------------------------------
__global__ __launch_bounds__(64) void k_inter(float* __restrict__ cs)
{
    int b = blockIdx.x / HH;
    int h = blockIdx.x % HH;
    int d = threadIdx.x;

    float s0 = 0.f, s1 = 0.f;
#pragma unroll 8
    for (int c = 0; c < NCH; c++) {
        size_t w = ((size_t)b * NCH + c) * HH + h;
        cs[(w * 2 + 0) * 64 + d] = s0;
        cs[(w * 2 + 1) * 64 + d] = s1;
        const float* at = g_At + w * 4;
        float a00 = __ldg(at + 0), a01 = __ldg(at + 1);
        float a10 = __ldg(at + 2), a11 = __ldg(at + 3);
        float hf0 = __ldg(g_hfin + w * 128 + d);
        float hf1 = __ldg(g_hfin + w * 128 + 64 + d);
        float n0 = a00 * s0 + a01 * s1 + hf0;
        float n1 = a10 * s0 + a11 * s1 + hf1;
        s0 = n0; s1 = n1;
    }
}

extern "C" void kernel_launch(void* const* d_in, const int* in_sizes, int n_in,
                              void* d_out, int out_size)
{
    const float* A    = (const float*)d_in[0];
    const float* K    = (const float*)d_in[1];
    const float* V    = (const float*)d_in[2];
    const float* beta = (const float*)d_in[3];
    float* Y  = (float*)d_out;
    float* cs = Y + YSIZE;   // chunk_states tail of the output buffer

    // 2048 warps, 2 chunk-heads each
    k_local1<<<512, 128>>>(A, K, V, beta);
    k_inter<<<BB * HH, 64>>>(cs);
    k_local2<<<512, 128>>>(A, K, V, beta, cs, Y);
}

// round 6
// speedup vs baseline: 1.4571x; 1.1670x over previous
#include <cuda_runtime.h>

#define BB 2
#define LL 8192
#define HH 16
#define DD 64
#define CC 64
#define NCH 128                    // LL/CC
#define NW  (BB*NCH*HH)            // 4096 chunk-head work items
#define YSIZE ((size_t)BB*LL*HH*2*DD)   // 33,554,432
#define PF 8                       // prefetch depth (divides CC)

// Scratch: per-chunk final state + total gate
__device__ float g_hfin[(size_t)NW * 128];  // [w][row(2)][d(64)]
__device__ float g_At[(size_t)NW * 4];      // [w][2][2]

__device__ __forceinline__ float4 f4fma(float s, float4 x, float4 acc) {
    return make_float4(fmaf(s, x.x, acc.x), fmaf(s, x.y, acc.y),
                       fmaf(s, x.z, acc.z), fmaf(s, x.w, acc.w));
}
__device__ __forceinline__ float4 f4scale(float s, float4 x) {
    return make_float4(s * x.x, s * x.y, s * x.z, s * x.w);
}
__device__ __forceinline__ float f4dot(float4 a, float4 b) {
    return a.x*b.x + a.y*b.y + a.z*b.z + a.w*b.w;
}

// ---------------------------------------------------------------------------
// Intra-chunk scan core. FOUR chunk-heads per warp: 8-lane group per head,
// each lane owns d = 8g..8g+7 (two float4s). Reduction = 3 butterfly levels
// confined to the 8-lane group -> 6 SHFL per warp-step for 4 heads
// (1.5 SHFL/head-step vs 4 before; we are MIO/SHFL-throughput-bound).
// 8-deep register prefetch hides DRAM latency behind the scan chain.
// ---------------------------------------------------------------------------
template<bool EMIT_Y>
__device__ __forceinline__ void intra_scan(
    const float* __restrict__ Ag, const float* __restrict__ Kg,
    const float* __restrict__ Vg, const float* __restrict__ Bg,
    const float* __restrict__ cs, float* __restrict__ Y)
{
    int warp = (blockIdx.x * blockDim.x + threadIdx.x) >> 5;
    int lane = threadIdx.x & 31;
    int g    = lane & 7;                  // position within 8-lane group
    int hd   = 4 * warp + (lane >> 3);    // chunk-head for this group

    int h = hd % HH;
    int c = (hd / HH) % NCH;
    int b = hd / (HH * NCH);
    size_t base = ((size_t)b * LL + (size_t)c * CC) * HH + h;

    float4 aB[PF]; float2 vB[PF]; float bB[PF]; float4 kB[PF][2];
#pragma unroll
    for (int i = 0; i < PF; i++) {
        size_t idx = base + (size_t)i * HH;
        aB[i]    = __ldg((const float4*)(Ag + idx * 4));
        vB[i]    = __ldg((const float2*)(Vg + idx * 2));
        bB[i]    = __ldg(Bg + idx);
        kB[i][0] = __ldg((const float4*)(Kg + idx * 64 + 8 * g));
        kB[i][1] = __ldg((const float4*)(Kg + idx * 64 + 8 * g + 4));
    }

    float4 S0[2], S1[2];
    if (EMIT_Y) {
        const float4* sp = (const float4*)(cs + (size_t)hd * 128);
#pragma unroll
        for (int j = 0; j < 2; j++) {
            S0[j] = __ldg(sp + 2 * g + j);
            S1[j] = __ldg(sp + 16 + 2 * g + j);
        }
    }

    float4 h0[2], h1[2];
#pragma unroll
    for (int j = 0; j < 2; j++) {
        h0[j] = make_float4(0.f, 0.f, 0.f, 0.f);
        h1[j] = make_float4(0.f, 0.f, 0.f, 0.f);
    }
    float p00 = 1.f, p01 = 0.f, p10 = 0.f, p11 = 1.f;

    for (int t = 0; t < CC; t += PF) {
#pragma unroll
        for (int u = 0; u < PF; u++) {
            float4 a  = aB[u];
            float2 v  = vB[u];
            float  bt = bB[u];
            float4 k0 = kB[u][0], k1 = kB[u][1];

            int tn = t + u + PF;
            if (tn < CC) {
                size_t idx = base + (size_t)tn * HH;
                aB[u]    = __ldg((const float4*)(Ag + idx * 4));
                vB[u]    = __ldg((const float2*)(Vg + idx * 2));
                bB[u]    = __ldg(Bg + idx);
                kB[u][0] = __ldg((const float4*)(Kg + idx * 64 + 8 * g));
                kB[u][1] = __ldg((const float4*)(Kg + idx * 64 + 8 * g + 4));
            }

            // propagate: hp = A * h (2x2 gate per d-element)
            float4 hp0[2], hp1[2];
#pragma unroll
            for (int j = 0; j < 2; j++) {
                hp0[j] = f4fma(a.y, h1[j], f4scale(a.x, h0[j]));
                hp1[j] = f4fma(a.w, h1[j], f4scale(a.z, h0[j]));
            }

            // read = k . hp : 8-wide local dot, 3-level group reduce
            float r0 = f4dot(hp0[0], k0) + f4dot(hp0[1], k1);
            float r1 = f4dot(hp1[0], k0) + f4dot(hp1[1], k1);
#pragma unroll
            for (int o = 4; o; o >>= 1) {
                r0 += __shfl_xor_sync(0xffffffffu, r0, o);
                r1 += __shfl_xor_sync(0xffffffffu, r1, o);
            }

            float d0 = bt * (v.x - r0);
            float d1 = bt * (v.y - r1);
            h0[0] = f4fma(d0, k0, hp0[0]);  h0[1] = f4fma(d0, k1, hp0[1]);
            h1[0] = f4fma(d1, k0, hp1[0]);  h1[1] = f4fma(d1, k1, hp1[1]);

            // cumulative 2x2 gate product
            float q00 = a.x * p00 + a.y * p10;
            float q01 = a.x * p01 + a.y * p11;
            float q10 = a.z * p00 + a.w * p10;
            float q11 = a.z * p01 + a.w * p11;
            p00 = q00; p01 = q01; p10 = q10; p11 = q11;

            if (EMIT_Y) {
                size_t idx = base + (size_t)(t + u) * HH;
                float4* yo = (float4*)(Y + idx * 128);
#pragma unroll
                for (int j = 0; j < 2; j++) {
                    float4 y0 = f4fma(p01, S1[j], f4fma(p00, S0[j], h0[j]));
                    float4 y1 = f4fma(p11, S1[j], f4fma(p10, S0[j], h1[j]));
                    __stcs(yo + 2 * g + j,      y0);
                    __stcs(yo + 16 + 2 * g + j, y1);
                }
            }
        }
    }

    if (!EMIT_Y) {
        float4* hf = (float4*)(g_hfin + (size_t)hd * 128);
#pragma unroll
        for (int j = 0; j < 2; j++) {
            hf[2 * g + j]      = h0[j];
            hf[16 + 2 * g + j] = h1[j];
        }
        if (g == 0) {
            float* at = g_At + (size_t)hd * 4;
            at[0] = p00; at[1] = p01; at[2] = p10; at[3] = p11;
        }
    }
}

__global__ __launch_bounds__(128) void k_local1(
    const float* __restrict__ Ag, const float* __restrict__ Kg,
    const float* __restrict__ Vg, const float* __restrict__ Bg)
{
    intra_scan<false>(Ag, Kg, Vg, Bg, nullptr, nullptr);
}

__global__ __launch_bounds__(128) void k_local2(
    const float* __restrict__ Ag, const float* __restrict__ Kg,
    const float* __restrict__ Vg, const float* __restrict__ Bg,
    const float* __restrict__ cs, float* __restrict__ Y)
{
    intra_scan<true>(Ag, Kg, Vg, Bg, cs, Y);
}

// ---------------------------------------------------------------------------
// Inter-chunk scan per (b,h); writes chunk_states (pre-update carry) straight
// into the output tail. Loads are carry-independent -> pipelined by unroll.
// ---------------------------------------------------------------------------
__global__ __launch_bounds__(64) void k_inter(float* __restrict__ cs)
{
    int b = blockIdx.x / HH;
    int h = blockIdx.x % HH;
    int d = threadIdx.x;

    float s0 = 0.f, s1 = 0.f;
#pragma unroll 8
    for (int c = 0; c < NCH; c++) {
        size_t w = ((size_t)b * NCH + c) * HH + h;
        cs[(w * 2 + 0) * 64 + d] = s0;
        cs[(w * 2 + 1) * 64 + d] = s1;
        const float* at = g_At + w * 4;
        float a00 = __ldg(at + 0), a01 = __ldg(at + 1);
        float a10 = __ldg(at + 2), a11 = __ldg(at + 3);
        float hf0 = __ldg(g_hfin + w * 128 + d);
        float hf1 = __ldg(g_hfin + w * 128 + 64 + d);
        float n0 = a00 * s0 + a01 * s1 + hf0;
        float n1 = a10 * s0 + a11 * s1 + hf1;
        s0 = n0; s1 = n1;
    }
}

extern "C" void kernel_launch(void* const* d_in, const int* in_sizes, int n_in,
                              void* d_out, int out_size)
{
    const float* A    = (const float*)d_in[0];
    const float* K    = (const float*)d_in[1];
    const float* V    = (const float*)d_in[2];
    const float* beta = (const float*)d_in[3];
    float* Y  = (float*)d_out;
    float* cs = Y + YSIZE;   // chunk_states tail of the output buffer

    // 1024 warps, 4 chunk-heads each
    k_local1<<<256, 128>>>(A, K, V, beta);
    k_inter<<<BB * HH, 64>>>(cs);
    k_local2<<<256, 128>>>(A, K, V, beta, cs, Y);
}

// round 7
// speedup vs baseline: 1.5322x; 1.0515x over previous
#include <cuda_runtime.h>

#define BB 2
#define LL 8192
#define HH 16
#define DD 64
#define CC 64
#define NCH 128                    // LL/CC
#define NW  (BB*NCH*HH)            // 4096 chunk-head work items
#define YSIZE ((size_t)BB*LL*HH*2*DD)   // 33,554,432
#define PF 8                       // prefetch depth (divides CC)

// Scratch: per-chunk final state + total gate + per-step replay data
__device__ float g_hfin[(size_t)NW * 128];     // [w][row(2)][d(64)]
__device__ float g_At[(size_t)NW * 4];         // [w][2][2]
__device__ float g_e[(size_t)NW * CC * 2];     // e_t = P_t^{-1} d_t
__device__ float g_P[(size_t)NW * CC * 4];     // inclusive cumulative gate P_t

__device__ __forceinline__ float4 f4fma(float s, float4 x, float4 acc) {
    return make_float4(fmaf(s, x.x, acc.x), fmaf(s, x.y, acc.y),
                       fmaf(s, x.z, acc.z), fmaf(s, x.w, acc.w));
}
__device__ __forceinline__ float4 f4scale(float s, float4 x) {
    return make_float4(s * x.x, s * x.y, s * x.z, s * x.w);
}
__device__ __forceinline__ float f4dot(float4 a, float4 b) {
    return a.x*b.x + a.y*b.y + a.z*b.z + a.w*b.w;
}

// ---------------------------------------------------------------------------
// Pass 1: intra-chunk scan. FOUR chunk-heads per warp (8 lanes each, 8 d per
// lane). Emits final_h + total_A (for the inter-chunk scan) AND the per-step
// replay pair (e_t, P_t) so pass 3 never has to redo the serial reductions.
// ---------------------------------------------------------------------------
__global__ __launch_bounds__(128) void k_local1(
    const float* __restrict__ Ag, const float* __restrict__ Kg,
    const float* __restrict__ Vg, const float* __restrict__ Bg)
{
    int warp = (blockIdx.x * blockDim.x + threadIdx.x) >> 5;
    int lane = threadIdx.x & 31;
    int g    = lane & 7;                  // position within 8-lane group
    int hd   = 4 * warp + (lane >> 3);    // chunk-head for this group

    int h = hd % HH;
    int c = (hd / HH) % NCH;
    int b = hd / (HH * NCH);
    size_t base = ((size_t)b * LL + (size_t)c * CC) * HH + h;
    size_t eb   = (size_t)hd * CC;

    float4 aB[PF]; float2 vB[PF]; float bB[PF]; float4 kB[PF][2];
#pragma unroll
    for (int i = 0; i < PF; i++) {
        size_t idx = base + (size_t)i * HH;
        aB[i]    = __ldg((const float4*)(Ag + idx * 4));
        vB[i]    = __ldg((const float2*)(Vg + idx * 2));
        bB[i]    = __ldg(Bg + idx);
        kB[i][0] = __ldg((const float4*)(Kg + idx * 64 + 8 * g));
        kB[i][1] = __ldg((const float4*)(Kg + idx * 64 + 8 * g + 4));
    }

    float4 h0[2], h1[2];
#pragma unroll
    for (int j = 0; j < 2; j++) {
        h0[j] = make_float4(0.f, 0.f, 0.f, 0.f);
        h1[j] = make_float4(0.f, 0.f, 0.f, 0.f);
    }
    float p00 = 1.f, p01 = 0.f, p10 = 0.f, p11 = 1.f;

    for (int t = 0; t < CC; t += PF) {
#pragma unroll
        for (int u = 0; u < PF; u++) {
            float4 a  = aB[u];
            float2 v  = vB[u];
            float  bt = bB[u];
            float4 k0 = kB[u][0], k1 = kB[u][1];

            int tn = t + u + PF;
            if (tn < CC) {
                size_t idx = base + (size_t)tn * HH;
                aB[u]    = __ldg((const float4*)(Ag + idx * 4));
                vB[u]    = __ldg((const float2*)(Vg + idx * 2));
                bB[u]    = __ldg(Bg + idx);
                kB[u][0] = __ldg((const float4*)(Kg + idx * 64 + 8 * g));
                kB[u][1] = __ldg((const float4*)(Kg + idx * 64 + 8 * g + 4));
            }

            // propagate: hp = A * h
            float4 hp0[2], hp1[2];
#pragma unroll
            for (int j = 0; j < 2; j++) {
                hp0[j] = f4fma(a.y, h1[j], f4scale(a.x, h0[j]));
                hp1[j] = f4fma(a.w, h1[j], f4scale(a.z, h0[j]));
            }

            // read = k . hp : 8-wide local dot, 3-level group reduce
            float r0 = f4dot(hp0[0], k0) + f4dot(hp0[1], k1);
            float r1 = f4dot(hp1[0], k0) + f4dot(hp1[1], k1);
#pragma unroll
            for (int o = 4; o; o >>= 1) {
                r0 += __shfl_xor_sync(0xffffffffu, r0, o);
                r1 += __shfl_xor_sync(0xffffffffu, r1, o);
            }

            float d0 = bt * (v.x - r0);
            float d1 = bt * (v.y - r1);
            h0[0] = f4fma(d0, k0, hp0[0]);  h0[1] = f4fma(d0, k1, hp0[1]);
            h1[0] = f4fma(d1, k0, hp1[0]);  h1[1] = f4fma(d1, k1, hp1[1]);

            // cumulative 2x2 gate product (inclusive)
            float q00 = a.x * p00 + a.y * p10;
            float q01 = a.x * p01 + a.y * p11;
            float q10 = a.z * p00 + a.w * p10;
            float q11 = a.z * p01 + a.w * p11;
            p00 = q00; p01 = q01; p10 = q10; p11 = q11;

            // e_t = P_t^{-1} d_t ; store (e_t, P_t) for the replay pass
            if (g == 0) {
                float rdet = __frcp_rn(p00 * p11 - p01 * p10);
                float e0 = (p11 * d0 - p01 * d1) * rdet;
                float e1 = (p00 * d1 - p10 * d0) * rdet;
                size_t o = eb + (size_t)(t + u);
                ((float2*)g_e)[o] = make_float2(e0, e1);
                ((float4*)g_P)[o] = make_float4(p00, p01, p10, p11);
            }
        }
    }

    float4* hf = (float4*)(g_hfin + (size_t)hd * 128);
#pragma unroll
    for (int j = 0; j < 2; j++) {
        hf[2 * g + j]      = h0[j];
        hf[16 + 2 * g + j] = h1[j];
    }
    if (g == 0) {
        float* at = g_At + (size_t)hd * 4;
        at[0] = p00; at[1] = p01; at[2] = p10; at[3] = p11;
    }
}

// ---------------------------------------------------------------------------
// Pass 2: inter-chunk scan per (b,h); writes chunk_states (pre-update carry)
// straight into the output tail.
// ---------------------------------------------------------------------------
__global__ __launch_bounds__(64) void k_inter(float* __restrict__ cs)
{
    int b = blockIdx.x / HH;
    int h = blockIdx.x % HH;
    int d = threadIdx.x;

    float s0 = 0.f, s1 = 0.f;
#pragma unroll 8
    for (int c = 0; c < NCH; c++) {
        size_t w = ((size_t)b * NCH + c) * HH + h;
        cs[(w * 2 + 0) * 64 + d] = s0;
        cs[(w * 2 + 1) * 64 + d] = s1;
        const float* at = g_At + w * 4;
        float a00 = __ldg(at + 0), a01 = __ldg(at + 1);
        float a10 = __ldg(at + 2), a11 = __ldg(at + 3);
        float hf0 = __ldg(g_hfin + w * 128 + d);
        float hf1 = __ldg(g_hfin + w * 128 + 64 + d);
        float n0 = a00 * s0 + a01 * s1 + hf0;
        float n1 = a10 * s0 + a11 * s1 + hf1;
        s0 = n0; s1 = n1;
    }
}

// ---------------------------------------------------------------------------
// Pass 3: shuffle-free replay.  Y_t = P_t * u_t  with  u_t = u_{t-1} + e_t k_t^T,
// u initialized to the chunk carry s (so the inter-chunk correction is folded
// in for free). TWO heads per warp, 16 lanes each, 4 d-values per lane.
// Pure streaming: reads K + (e,P), writes Y. No reductions at all.
// ---------------------------------------------------------------------------
__global__ __launch_bounds__(128) void k_replay(
    const float* __restrict__ Kg, const float* __restrict__ cs,
    float* __restrict__ Y)
{
    int warp = (blockIdx.x * blockDim.x + threadIdx.x) >> 5;
    int lane = threadIdx.x & 31;
    int g    = lane & 15;
    int hd   = 2 * warp + (lane >> 4);

    int h = hd % HH;
    int c = (hd / HH) % NCH;
    int b = hd / (HH * NCH);
    size_t base = ((size_t)b * LL + (size_t)c * CC) * HH + h;
    size_t eb   = (size_t)hd * CC;

    const float4* sp = (const float4*)(cs + (size_t)hd * 128);
    float4 u0 = __ldg(sp + g);        // row0, d = 4g..4g+3  (u := s)
    float4 u1 = __ldg(sp + 16 + g);   // row1

    float4 kB[PF]; float2 eB[PF]; float4 pB[PF];
#pragma unroll
    for (int i = 0; i < PF; i++) {
        size_t idx = base + (size_t)i * HH;
        kB[i] = __ldg((const float4*)(Kg + idx * 64 + 4 * g));
        eB[i] = __ldg(((const float2*)g_e) + eb + i);
        pB[i] = __ldg(((const float4*)g_P) + eb + i);
    }

    for (int t = 0; t < CC; t += PF) {
#pragma unroll
        for (int u = 0; u < PF; u++) {
            float4 kk = kB[u];
            float2 e  = eB[u];
            float4 P  = pB[u];

            int tn = t + u + PF;
            if (tn < CC) {
                size_t idx = base + (size_t)tn * HH;
                kB[u] = __ldg((const float4*)(Kg + idx * 64 + 4 * g));
                eB[u] = __ldg(((const float2*)g_e) + eb + tn);
                pB[u] = __ldg(((const float4*)g_P) + eb + tn);
            }

            u0 = f4fma(e.x, kk, u0);
            u1 = f4fma(e.y, kk, u1);

            float4 y0 = f4fma(P.y, u1, f4scale(P.x, u0));
            float4 y1 = f4fma(P.w, u1, f4scale(P.z, u0));

            size_t idx = base + (size_t)(t + u) * HH;
            float4* yo = (float4*)(Y + idx * 128);
            __stcs(yo + g,      y0);
            __stcs(yo + 16 + g, y1);
        }
    }
}

extern "C" void kernel_launch(void* const* d_in, const int* in_sizes, int n_in,
                              void* d_out, int out_size)
{
    const float* A    = (const float*)d_in[0];
    const float* K    = (const float*)d_in[1];
    const float* V    = (const float*)d_in[2];
    const float* beta = (const float*)d_in[3];
    float* Y  = (float*)d_out;
    float* cs = Y + YSIZE;   // chunk_states tail of the output buffer

    k_local1<<<256, 128>>>(A, K, V, beta);   // 1024 warps, 4 heads each
    k_inter<<<BB * HH, 64>>>(cs);
    k_replay<<<512, 128>>>(K, cs, Y);        // 2048 warps, 2 heads each
}

// round 11
// speedup vs baseline: 1.6472x; 1.0751x over previous
#include <cuda_runtime.h>

#define BB 2
#define LL 8192
#define HH 16
#define DD 64
#define CC 64
#define NCH 128                    // LL/CC
#define NW  (BB*NCH*HH)            // 4096 chunk-head work items
#define YSIZE ((size_t)BB*LL*HH*2*DD)   // 33,554,432
#define PF 8                       // prefetch depth (divides CC)

// Scratch
__device__ float g_hfin[(size_t)NW * 128];   // per-chunk final local state
__device__ float g_At[(size_t)NW * 4];       // per-chunk total 2x2 gate
__device__ float g_d[(size_t)NW * CC * 2];   // raw per-step delta d_t

__device__ __forceinline__ float4 f4fma(float s, float4 x, float4 acc) {
    return make_float4(fmaf(s, x.x, acc.x), fmaf(s, x.y, acc.y),
                       fmaf(s, x.z, acc.z), fmaf(s, x.w, acc.w));
}
__device__ __forceinline__ float4 f4scale(float s, float4 x) {
    return make_float4(s * x.x, s * x.y, s * x.z, s * x.w);
}
__device__ __forceinline__ float f4dot(float4 a, float4 b) {
    return a.x*b.x + a.y*b.y + a.z*b.z + a.w*b.w;
}

// ---------------------------------------------------------------------------
// Pass 1: intra-chunk scan (CHUNK=64, reference semantics). FOUR chunk-heads
// per warp (8 lanes each, 8 d-values per lane). Emits final_h + total_A for
// the inter-chunk scan, and the raw per-step delta d_t for the replay pass.
// ---------------------------------------------------------------------------
__global__ __launch_bounds__(128) void k_local1(
    const float* __restrict__ Ag, const float* __restrict__ Kg,
    const float* __restrict__ Vg, const float* __restrict__ Bg)
{
    int warp = (blockIdx.x * blockDim.x + threadIdx.x) >> 5;
    int lane = threadIdx.x & 31;
    int g    = lane & 7;
    int hd   = 4 * warp + (lane >> 3);

    int h = hd % HH;
    int c = (hd / HH) % NCH;
    int b = hd / (HH * NCH);
    size_t base = ((size_t)b * LL + (size_t)c * CC) * HH + h;
    size_t db   = (size_t)hd * CC;

    float4 aB[PF]; float2 vB[PF]; float bB[PF]; float4 kB[PF][2];
#pragma unroll
    for (int i = 0; i < PF; i++) {
        size_t idx = base + (size_t)i * HH;
        aB[i]    = __ldg((const float4*)(Ag + idx * 4));
        vB[i]    = __ldg((const float2*)(Vg + idx * 2));
        bB[i]    = __ldg(Bg + idx);
        kB[i][0] = __ldg((const float4*)(Kg + idx * 64 + 8 * g));
        kB[i][1] = __ldg((const float4*)(Kg + idx * 64 + 8 * g + 4));
    }

    float4 h0[2], h1[2];
#pragma unroll
    for (int j = 0; j < 2; j++) {
        h0[j] = make_float4(0.f, 0.f, 0.f, 0.f);
        h1[j] = make_float4(0.f, 0.f, 0.f, 0.f);
    }
    float p00 = 1.f, p01 = 0.f, p10 = 0.f, p11 = 1.f;

    for (int t = 0; t < CC; t += PF) {
#pragma unroll
        for (int u = 0; u < PF; u++) {
            float4 a  = aB[u];
            float2 v  = vB[u];
            float  bt = bB[u];
            float4 k0 = kB[u][0], k1 = kB[u][1];

            int tn = t + u + PF;
            if (tn < CC) {
                size_t idx = base + (size_t)tn * HH;
                aB[u]    = __ldg((const float4*)(Ag + idx * 4));
                vB[u]    = __ldg((const float2*)(Vg + idx * 2));
                bB[u]    = __ldg(Bg + idx);
                kB[u][0] = __ldg((const float4*)(Kg + idx * 64 + 8 * g));
                kB[u][1] = __ldg((const float4*)(Kg + idx * 64 + 8 * g + 4));
            }

            // propagate: hp = A * h
            float4 hp0[2], hp1[2];
#pragma unroll
            for (int j = 0; j < 2; j++) {
                hp0[j] = f4fma(a.y, h1[j], f4scale(a.x, h0[j]));
                hp1[j] = f4fma(a.w, h1[j], f4scale(a.z, h0[j]));
            }

            // read = k . hp : 8-wide local dot, 3-level group reduce
            float r0 = f4dot(hp0[0], k0) + f4dot(hp0[1], k1);
            float r1 = f4dot(hp1[0], k0) + f4dot(hp1[1], k1);
#pragma unroll
            for (int o = 4; o; o >>= 1) {
                r0 += __shfl_xor_sync(0xffffffffu, r0, o);
                r1 += __shfl_xor_sync(0xffffffffu, r1, o);
            }

            float d0 = bt * (v.x - r0);
            float d1 = bt * (v.y - r1);
            h0[0] = f4fma(d0, k0, hp0[0]);  h0[1] = f4fma(d0, k1, hp0[1]);
            h1[0] = f4fma(d1, k0, hp1[0]);  h1[1] = f4fma(d1, k1, hp1[1]);

            // cumulative 2x2 gate product (needed for total_A only)
            float q00 = a.x * p00 + a.y * p10;
            float q01 = a.x * p01 + a.y * p11;
            float q10 = a.z * p00 + a.w * p10;
            float q11 = a.z * p01 + a.w * p11;
            p00 = q00; p01 = q01; p10 = q10; p11 = q11;

            if (g == 0)
                ((float2*)g_d)[db + (size_t)(t + u)] = make_float2(d0, d1);
        }
    }

    float4* hf = (float4*)(g_hfin + (size_t)hd * 128);
#pragma unroll
    for (int j = 0; j < 2; j++) {
        hf[2 * g + j]      = h0[j];
        hf[16 + 2 * g + j] = h1[j];
    }
    if (g == 0) {
        float* at = g_At + (size_t)hd * 4;
        at[0] = p00; at[1] = p01; at[2] = p10; at[3] = p11;
    }
}

// ---------------------------------------------------------------------------
// Pass 2: inter-chunk scan per (b,h); writes chunk_states (pre-update carry)
// straight into the output tail.
// ---------------------------------------------------------------------------
__global__ __launch_bounds__(64) void k_inter(float* __restrict__ cs)
{
    int b = blockIdx.x / HH;
    int h = blockIdx.x % HH;
    int d = threadIdx.x;

    float s0 = 0.f, s1 = 0.f;
#pragma unroll 8
    for (int c = 0; c < NCH; c++) {
        size_t w = ((size_t)b * NCH + c) * HH + h;
        cs[(w * 2 + 0) * 64 + d] = s0;
        cs[(w * 2 + 1) * 64 + d] = s1;
        const float* at = g_At + w * 4;
        float a00 = __ldg(at + 0), a01 = __ldg(at + 1);
        float a10 = __ldg(at + 2), a11 = __ldg(at + 3);
        float hf0 = __ldg(g_hfin + w * 128 + d);
        float hf1 = __ldg(g_hfin + w * 128 + 64 + d);
        float n0 = a00 * s0 + a01 * s1 + hf0;
        float n1 = a10 * s0 + a11 * s1 + hf1;
        s0 = n0; s1 = n1;
    }
}

// ---------------------------------------------------------------------------
// Pass 3: shuffle-free replay in d-form:
//   v := s_chunk;  v_t = A_t v_{t-1} + d_t k_t^T;  Y_t = v_t.
// (A_t local_{t-1} + A_t P_{t-1} s + d_t k = local_t + P_t s — exact.)
// TWO chunk-heads per warp, 16 lanes each, 4 d-values per lane.
// ---------------------------------------------------------------------------
__global__ __launch_bounds__(128) void k_replay(
    const float* __restrict__ Ag, const float* __restrict__ Kg,
    const float* __restrict__ cs, float* __restrict__ Y)
{
    int warp = (blockIdx.x * blockDim.x + threadIdx.x) >> 5;
    int lane = threadIdx.x & 31;
    int g    = lane & 15;
    int hd   = 2 * warp + (lane >> 4);

    int h = hd % HH;
    int c = (hd / HH) % NCH;
    int b = hd / (HH * NCH);
    size_t base = ((size_t)b * LL + (size_t)c * CC) * HH + h;
    size_t db   = (size_t)hd * CC;

    const float4* sp = (const float4*)(cs + (size_t)hd * 128);
    float4 v0 = __ldg(sp + g);        // row0, d = 4g..4g+3  (v := s)
    float4 v1 = __ldg(sp + 16 + g);   // row1

    float4 kB[PF]; float2 dB[PF]; float4 aB[PF];
#pragma unroll
    for (int i = 0; i < PF; i++) {
        size_t idx = base + (size_t)i * HH;
        kB[i] = __ldg((const float4*)(Kg + idx * 64 + 4 * g));
        dB[i] = __ldg(((const float2*)g_d) + db + i);
        aB[i] = __ldg((const float4*)(Ag + idx * 4));
    }

    for (int t = 0; t < CC; t += PF) {
#pragma unroll
        for (int u = 0; u < PF; u++) {
            float4 kk = kB[u];
            float2 dd = dB[u];
            float4 a  = aB[u];

            int tn = t + u + PF;
            if (tn < CC) {
                size_t idx = base + (size_t)tn * HH;
                kB[u] = __ldg((const float4*)(Kg + idx * 64 + 4 * g));
                dB[u] = __ldg(((const float2*)g_d) + db + tn);
                aB[u] = __ldg((const float4*)(Ag + idx * 4));
            }

            float4 n0 = f4fma(dd.x, kk, f4fma(a.y, v1, f4scale(a.x, v0)));
            float4 n1 = f4fma(dd.y, kk, f4fma(a.w, v1, f4scale(a.z, v0)));
            v0 = n0; v1 = n1;

            size_t idx = base + (size_t)(t + u) * HH;
            float4* yo = (float4*)(Y + idx * 128);
            __stcs(yo + g,      v0);
            __stcs(yo + 16 + g, v1);
        }
    }
}

extern "C" void kernel_launch(void* const* d_in, const int* in_sizes, int n_in,
                              void* d_out, int out_size)
{
    const float* A    = (const float*)d_in[0];
    const float* K    = (const float*)d_in[1];
    const float* V    = (const float*)d_in[2];
    const float* beta = (const float*)d_in[3];
    float* Y  = (float*)d_out;
    float* cs = Y + YSIZE;   // chunk_states tail of the output buffer

    k_local1<<<NW / 16, 128>>>(A, K, V, beta);   // 1024 warps, 4 heads each
    k_inter<<<BB * HH, 64>>>(cs);
    k_replay<<<NW / 8, 128>>>(A, K, cs, Y);      // 2048 warps, 2 heads each
}

// round 12
// speedup vs baseline: 1.6577x; 1.0063x over previous
#include <cuda_runtime.h>

#define BB 2
#define LL 8192
#define HH 16
#define DD 64
#define CC 64
#define NCH 128                    // LL/CC
#define NW  (BB*NCH*HH)            // 4096 chunk-head work items
#define YSIZE ((size_t)BB*LL*HH*2*DD)   // 33,554,432
#define PF 8                       // prefetch depth
#define SEG 16                     // replay segment length
#define NSEG (CC/SEG)              // 4 segments per chunk

// Scratch
__device__ float g_cp[(size_t)NW * 4 * 128];  // checkpoints t=15,31,47,63: local_h
__device__ float g_Pcp[(size_t)NW * 4 * 4];   // checkpoints: inclusive cum gate P
__device__ float g_d[(size_t)NW * CC * 2];    // raw per-step delta d_t

__device__ __forceinline__ float4 f4fma(float s, float4 x, float4 acc) {
    return make_float4(fmaf(s, x.x, acc.x), fmaf(s, x.y, acc.y),
                       fmaf(s, x.z, acc.z), fmaf(s, x.w, acc.w));
}
__device__ __forceinline__ float4 f4scale(float s, float4 x) {
    return make_float4(s * x.x, s * x.y, s * x.z, s * x.w);
}
__device__ __forceinline__ float f4dot(float4 a, float4 b) {
    return a.x*b.x + a.y*b.y + a.z*b.z + a.w*b.w;
}

// ---------------------------------------------------------------------------
// Pass 1: intra-chunk scan (CHUNK=64, reference semantics). FOUR chunk-heads
// per warp (8 lanes each, 8 d-values per lane). Emits per-step delta d_t and
// checkpoints (local_h, P) every 16 steps; checkpoint 3 doubles as
// final_h/total_A for the inter-chunk scan.
// ---------------------------------------------------------------------------
__global__ __launch_bounds__(128) void k_local1(
    const float* __restrict__ Ag, const float* __restrict__ Kg,
    const float* __restrict__ Vg, const float* __restrict__ Bg)
{
    int warp = (blockIdx.x * blockDim.x + threadIdx.x) >> 5;
    int lane = threadIdx.x & 31;
    int g    = lane & 7;
    int hd   = 4 * warp + (lane >> 3);

    int h = hd % HH;
    int c = (hd / HH) % NCH;
    int b = hd / (HH * NCH);
    size_t base = ((size_t)b * LL + (size_t)c * CC) * HH + h;
    size_t db   = (size_t)hd * CC;

    float4 aB[PF]; float2 vB[PF]; float bB[PF]; float4 kB[PF][2];
#pragma unroll
    for (int i = 0; i < PF; i++) {
        size_t idx = base + (size_t)i * HH;
        aB[i]    = __ldg((const float4*)(Ag + idx * 4));
        vB[i]    = __ldg((const float2*)(Vg + idx * 2));
        bB[i]    = __ldg(Bg + idx);
        kB[i][0] = __ldg((const float4*)(Kg + idx * 64 + 8 * g));
        kB[i][1] = __ldg((const float4*)(Kg + idx * 64 + 8 * g + 4));
    }

    float4 h0[2], h1[2];
#pragma unroll
    for (int j = 0; j < 2; j++) {
        h0[j] = make_float4(0.f, 0.f, 0.f, 0.f);
        h1[j] = make_float4(0.f, 0.f, 0.f, 0.f);
    }
    float p00 = 1.f, p01 = 0.f, p10 = 0.f, p11 = 1.f;

    for (int t = 0; t < CC; t += PF) {
#pragma unroll
        for (int u = 0; u < PF; u++) {
            float4 a  = aB[u];
            float2 v  = vB[u];
            float  bt = bB[u];
            float4 k0 = kB[u][0], k1 = kB[u][1];

            int tn = t + u + PF;
            if (tn < CC) {
                size_t idx = base + (size_t)tn * HH;
                aB[u]    = __ldg((const float4*)(Ag + idx * 4));
                vB[u]    = __ldg((const float2*)(Vg + idx * 2));
                bB[u]    = __ldg(Bg + idx);
                kB[u][0] = __ldg((const float4*)(Kg + idx * 64 + 8 * g));
                kB[u][1] = __ldg((const float4*)(Kg + idx * 64 + 8 * g + 4));
            }

            // propagate: hp = A * h
            float4 hp0[2], hp1[2];
#pragma unroll
            for (int j = 0; j < 2; j++) {
                hp0[j] = f4fma(a.y, h1[j], f4scale(a.x, h0[j]));
                hp1[j] = f4fma(a.w, h1[j], f4scale(a.z, h0[j]));
            }

            // read = k . hp : 8-wide local dot, 3-level group reduce
            float r0 = f4dot(hp0[0], k0) + f4dot(hp0[1], k1);
            float r1 = f4dot(hp1[0], k0) + f4dot(hp1[1], k1);
#pragma unroll
            for (int o = 4; o; o >>= 1) {
                r0 += __shfl_xor_sync(0xffffffffu, r0, o);
                r1 += __shfl_xor_sync(0xffffffffu, r1, o);
            }

            float d0 = bt * (v.x - r0);
            float d1 = bt * (v.y - r1);
            h0[0] = f4fma(d0, k0, hp0[0]);  h0[1] = f4fma(d0, k1, hp0[1]);
            h1[0] = f4fma(d1, k0, hp1[0]);  h1[1] = f4fma(d1, k1, hp1[1]);

            // cumulative 2x2 gate product (inclusive)
            float q00 = a.x * p00 + a.y * p10;
            float q01 = a.x * p01 + a.y * p11;
            float q10 = a.z * p00 + a.w * p10;
            float q11 = a.z * p01 + a.w * p11;
            p00 = q00; p01 = q01; p10 = q10; p11 = q11;

            if (g == 0)
                ((float2*)g_d)[db + (size_t)(t + u)] = make_float2(d0, d1);

            // checkpoint every SEG steps (t+u = 15, 31, 47, 63)
            if (((t + u) & (SEG - 1)) == SEG - 1) {
                int j = (t + u) >> 4;
                float4* cp = (float4*)(g_cp + ((size_t)hd * 4 + j) * 128);
                cp[2 * g + 0]      = h0[0];
                cp[2 * g + 1]      = h0[1];
                cp[16 + 2 * g + 0] = h1[0];
                cp[16 + 2 * g + 1] = h1[1];
                if (g == 0)
                    ((float4*)g_Pcp)[(size_t)hd * 4 + j] =
                        make_float4(p00, p01, p10, p11);
            }
        }
    }
}

// ---------------------------------------------------------------------------
// Pass 2: inter-chunk scan per (b,h); consumes checkpoint 3 (final_h/total_A);
// writes chunk_states (pre-update carry) straight into the output tail.
// ---------------------------------------------------------------------------
__global__ __launch_bounds__(64) void k_inter(float* __restrict__ cs)
{
    int b = blockIdx.x / HH;
    int h = blockIdx.x % HH;
    int d = threadIdx.x;

    float s0 = 0.f, s1 = 0.f;
#pragma unroll 8
    for (int c = 0; c < NCH; c++) {
        size_t w = ((size_t)b * NCH + c) * HH + h;
        cs[(w * 2 + 0) * 64 + d] = s0;
        cs[(w * 2 + 1) * 64 + d] = s1;
        const float* at = g_Pcp + (w * 4 + 3) * 4;
        float a00 = __ldg(at + 0), a01 = __ldg(at + 1);
        float a10 = __ldg(at + 2), a11 = __ldg(at + 3);
        const float* hf = g_cp + (w * 4 + 3) * 128;
        float hf0 = __ldg(hf + d);
        float hf1 = __ldg(hf + 64 + d);
        float n0 = a00 * s0 + a01 * s1 + hf0;
        float n1 = a10 * s0 + a11 * s1 + hf1;
        s0 = n0; s1 = n1;
    }
}

// ---------------------------------------------------------------------------
// Pass 3: checkpointed shuffle-free replay. One 16-lane group per
// (chunk-head, segment); 4 segments per chunk -> 16384 units, 8192 warps.
//   v_init = cp_h[seg-1] + P_cp[seg-1] * s   (seg 0: v_init = s)
//   v_t = A_t v_{t-1} + d_t k_t^T ;  Y_t = v_t      (exact playback)
// ---------------------------------------------------------------------------
__global__ __launch_bounds__(128) void k_replay(
    const float* __restrict__ Ag, const float* __restrict__ Kg,
    const float* __restrict__ cs, float* __restrict__ Y)
{
    int warp = (blockIdx.x * blockDim.x + threadIdx.x) >> 5;
    int lane = threadIdx.x & 31;
    int g    = lane & 15;
    int uid  = 2 * warp + (lane >> 4);   // 0..16383, hd fastest
    int hd   = uid & (NW - 1);
    int seg  = uid >> 12;                // uid / NW

    int h = hd % HH;
    int c = (hd / HH) % NCH;
    int b = hd / (HH * NCH);
    int t0 = seg * SEG;
    size_t base = ((size_t)b * LL + (size_t)c * CC + t0) * HH + h;
    size_t db   = (size_t)hd * CC + t0;

    const float4* sp = (const float4*)(cs + (size_t)hd * 128);
    float4 s0 = __ldg(sp + g);
    float4 s1 = __ldg(sp + 16 + g);

    float4 v0, v1;
    if (seg == 0) {
        v0 = s0; v1 = s1;
    } else {
        const float4* cp = (const float4*)(g_cp + ((size_t)hd * 4 + seg - 1) * 128);
        float4 c0 = __ldg(cp + g);
        float4 c1 = __ldg(cp + 16 + g);
        float4 P  = __ldg(((const float4*)g_Pcp) + (size_t)hd * 4 + seg - 1);
        v0 = f4fma(P.y, s1, f4fma(P.x, s0, c0));
        v1 = f4fma(P.w, s1, f4fma(P.z, s0, c1));
    }

    float4 kB[PF]; float2 dB[PF]; float4 aB[PF];
#pragma unroll
    for (int i = 0; i < PF; i++) {
        size_t idx = base + (size_t)i * HH;
        kB[i] = __ldg((const float4*)(Kg + idx * 64 + 4 * g));
        dB[i] = __ldg(((const float2*)g_d) + db + i);
        aB[i] = __ldg((const float4*)(Ag + idx * 4));
    }

    for (int t = 0; t < SEG; t += PF) {
#pragma unroll
        for (int u = 0; u < PF; u++) {
            float4 kk = kB[u];
            float2 dd = dB[u];
            float4 a  = aB[u];

            int tn = t + u + PF;
            if (tn < SEG) {
                size_t idx = base + (size_t)tn * HH;
                kB[u] = __ldg((const float4*)(Kg + idx * 64 + 4 * g));
                dB[u] = __ldg(((const float2*)g_d) + db + tn);
                aB[u] = __ldg((const float4*)(Ag + idx * 4));
            }

            float4 n0 = f4fma(dd.x, kk, f4fma(a.y, v1, f4scale(a.x, v0)));
            float4 n1 = f4fma(dd.y, kk, f4fma(a.w, v1, f4scale(a.z, v0)));
            v0 = n0; v1 = n1;

            size_t idx = base + (size_t)(t + u) * HH;
            float4* yo = (float4*)(Y + idx * 128);
            __stcs(yo + g,      v0);
            __stcs(yo + 16 + g, v1);
        }
    }
}

extern "C" void kernel_launch(void* const* d_in, const int* in_sizes, int n_in,
                              void* d_out, int out_size)
{
    const float* A    = (const float*)d_in[0];
    const float* K    = (const float*)d_in[1];
    const float* V    = (const float*)d_in[2];
    const float* beta = (const float*)d_in[3];
    float* Y  = (float*)d_out;
    float* cs = Y + YSIZE;   // chunk_states tail of the output buffer

    k_local1<<<NW / 16, 128>>>(A, K, V, beta);     // 1024 warps, 4 heads each
    k_inter<<<BB * HH, 64>>>(cs);
    k_replay<<<(NW * NSEG) / 8, 128>>>(A, K, cs, Y); // 8192 warps, 2 units each
}